// round 5
// baseline (speedup 1.0000x reference)
#include <cuda_runtime.h>
#include <cuda_bf16.h>

// GraphNorm: out = weight * (x - mean[batch]*mean_scale) / std[batch] + bias
// batch is SORTED -> segment g occupies the contiguous row range
// [lower_bound(batch, g), lower_bound(batch, g+1)).
//
// NOTE on batch dtype: reference says int64, but JAX default config (x64
// disabled) downcasts to int32 -> the device buffer is almost certainly
// int32. We probe the dtype in-bounds and branch (see sIsI64).
//
// One-pass stats via E[x^2]:
//   sub = x - s*m,  var(sub) = E[x^2] + m^2 * s * (s - 2)
// Output is affine per (segment, column):
//   A = w * rsqrt(var + eps),  B = bias - s*m*A,  out = x*A + B

#define EPS 1e-6f
#define NUM_SEGMENTS 4096   // fixed by problem setup (G)

__global__ __launch_bounds__(256) void graphnorm_kernel(
    const float* __restrict__ x,
    const void* __restrict__ batch_raw,
    int n,
    const float* __restrict__ weight,
    const float* __restrict__ bias,
    const float* __restrict__ mean_scale,
    float* __restrict__ out)
{
    const int g = blockIdx.x;
    const int t = threadIdx.x;
    const int q = t & 31;   // quad: owns columns [4q, 4q+4)
    const int r = t >> 5;   // row-lane: strides rows by 8

    __shared__ int sBounds[2];
    __shared__ int sIsI64;
    __shared__ float4 s_sum[8][32];
    __shared__ float4 s_sq [8][32];
    __shared__ float4 sA[32];
    __shared__ float4 sB[32];

    // Dtype probe: view buffer as u32[n] (in-bounds under either dtype).
    // Largest odd index j: int32 -> batch[j] near max (4095, nonzero);
    // int64 -> high word of an element (zero, since values < 2^31).
    if (t == 0) {
        int j = n - 1;
        if ((j & 1) == 0) j -= 1;          // make odd
        if (j < 1) j = 1;
        sIsI64 = (((const unsigned*)batch_raw)[j] == 0u) ? 1 : 0;
    }
    __syncthreads();
    const int isI64 = sIsI64;

    // Two threads each run one lower_bound over the sorted batch array.
    if (t == 0 || t == 32) {
        int key = g + (t == 32 ? 1 : 0);
        int lo = 0, hi = n;
        if (isI64) {
            const long long* b64 = (const long long*)batch_raw;
            long long k = (long long)key;
            while (lo < hi) {
                int mid = (lo + hi) >> 1;
                if (__ldg(&b64[mid]) < k) lo = mid + 1; else hi = mid;
            }
        } else {
            const int* b32 = (const int*)batch_raw;
            while (lo < hi) {
                int mid = (lo + hi) >> 1;
                if (__ldg(&b32[mid]) < key) lo = mid + 1; else hi = mid;
            }
        }
        sBounds[t == 32 ? 1 : 0] = lo;
    }
    __syncthreads();

    const int s = sBounds[0];
    const int e = sBounds[1];
    if (e <= s) return;   // empty segment: no rows owned, nothing to write

    const float4* __restrict__ xv = (const float4*)x;

    float4 sum = make_float4(0.f, 0.f, 0.f, 0.f);
    float4 sq  = make_float4(0.f, 0.f, 0.f, 0.f);

    // Pass 1: accumulate sum and sum-of-squares for owned columns.
    for (int i = s + r; i < e; i += 8) {
        float4 v = xv[(size_t)i * 32 + q];
        sum.x += v.x; sum.y += v.y; sum.z += v.z; sum.w += v.w;
        sq.x  += v.x * v.x; sq.y += v.y * v.y;
        sq.z  += v.z * v.z; sq.w += v.w * v.w;
    }
    s_sum[r][q] = sum;
    s_sq [r][q] = sq;
    __syncthreads();

    // Cross-warp tree reduce over the 8 row-lanes.
    #pragma unroll
    for (int off = 4; off > 0; off >>= 1) {
        if (r < off) {
            float4 a = s_sum[r][q], b = s_sum[r + off][q];
            a.x += b.x; a.y += b.y; a.z += b.z; a.w += b.w;
            s_sum[r][q] = a;
            float4 c = s_sq[r][q], d = s_sq[r + off][q];
            c.x += d.x; c.y += d.y; c.z += d.z; c.w += d.w;
            s_sq[r][q] = c;
        }
        __syncthreads();
    }

    // Warp 0: per-column affine coefficients A, B.
    if (r == 0) {
        float inv_cnt = 1.f / (float)(e - s);
        float4 tsum = s_sum[0][q];
        float4 tsq  = s_sq [0][q];
        float4 w4   = ((const float4*)weight)[q];
        float4 b4   = ((const float4*)bias)[q];
        float4 ms4  = ((const float4*)mean_scale)[q];

        float4 A, B;
        {
            float m = tsum.x * inv_cnt;
            float var = tsq.x * inv_cnt + m * m * ms4.x * (ms4.x - 2.f);
            A.x = w4.x * rsqrtf(var + EPS);
            B.x = b4.x - m * ms4.x * A.x;
        }
        {
            float m = tsum.y * inv_cnt;
            float var = tsq.y * inv_cnt + m * m * ms4.y * (ms4.y - 2.f);
            A.y = w4.y * rsqrtf(var + EPS);
            B.y = b4.y - m * ms4.y * A.y;
        }
        {
            float m = tsum.z * inv_cnt;
            float var = tsq.z * inv_cnt + m * m * ms4.z * (ms4.z - 2.f);
            A.z = w4.z * rsqrtf(var + EPS);
            B.z = b4.z - m * ms4.z * A.z;
        }
        {
            float m = tsum.w * inv_cnt;
            float var = tsq.w * inv_cnt + m * m * ms4.w * (ms4.w - 2.f);
            A.w = w4.w * rsqrtf(var + EPS);
            B.w = b4.w - m * ms4.w * A.w;
        }
        sA[q] = A;
        sB[q] = B;
    }
    __syncthreads();

    const float4 A = sA[q];
    const float4 B = sB[q];
    float4* __restrict__ ov = (float4*)out;

    // Pass 2: re-read rows (L2-hot) and emit x*A + B.
    for (int i = s + r; i < e; i += 8) {
        float4 v = xv[(size_t)i * 32 + q];
        float4 o;
        o.x = v.x * A.x + B.x;
        o.y = v.y * A.y + B.y;
        o.z = v.z * A.z + B.z;
        o.w = v.w * A.w + B.w;
        ov[(size_t)i * 32 + q] = o;
    }
}

extern "C" void kernel_launch(void* const* d_in, const int* in_sizes, int n_in,
                              void* d_out, int out_size) {
    const float* x          = (const float*)d_in[0];
    const void*  batch      = (const void*)d_in[1];
    // d_in[2] = num_segments (device scalar; grid sized by NUM_SEGMENTS)
    const float* weight     = (const float*)d_in[3];
    const float* bias       = (const float*)d_in[4];
    const float* mean_scale = (const float*)d_in[5];
    float*       out        = (float*)d_out;

    const int D = 128;
    const int N = in_sizes[0] / D;

    graphnorm_kernel<<<NUM_SEGMENTS, 256>>>(x, batch, N, weight, bias,
                                            mean_scale, out);
}